// round 2
// baseline (speedup 1.0000x reference)
#include <cuda_runtime.h>

// Problem constants
#define B_  4
#define T_  2048
#define C_  1024
#define H_  16
#define DH_ 64
#define M_ROWS (B_ * T_)      // 8192
#define QKV_N  (3 * C_)       // 3072

// Scratch (device globals: the sanctioned no-alloc path)
__device__ float g_qkv[(size_t)M_ROWS * QKV_N];   // 96 MB
__device__ float g_att[(size_t)M_ROWS * C_];      // 32 MB

// ---------------------------------------------------------------------------
// SGEMM: C[M,N] = A[M,K] @ B[K,N], row-major, M%128==0, N%128==0, K%8==0
// 128x128 block tile, 8x8 per-thread microtile, BK=8, 256 threads.
// ---------------------------------------------------------------------------
__global__ __launch_bounds__(256)
void sgemm_kernel(const float* __restrict__ A, const float* __restrict__ B,
                  float* __restrict__ C, int M, int N, int K)
{
    __shared__ float As[8][128];   // As[k][m] (A tile transposed)
    __shared__ float Bs[8][128];   // Bs[k][n]

    const int tid = threadIdx.x;
    const int bm  = blockIdx.y * 128;
    const int bn  = blockIdx.x * 128;

    // A tile load: 128 rows x 8 cols = 256 float4 -> 1 per thread
    const int arow = tid >> 1;
    const int acol = (tid & 1) << 2;
    // B tile load: 8 rows x 128 cols = 256 float4 -> 1 per thread
    const int brow = tid >> 5;
    const int bcol = (tid & 31) << 2;

    const int tm = (tid >> 4) << 3;   // 0..120
    const int tn = (tid & 15) << 3;   // 0..120

    float acc[8][8];
#pragma unroll
    for (int i = 0; i < 8; i++)
#pragma unroll
        for (int j = 0; j < 8; j++) acc[i][j] = 0.f;

    const float* Ap = A + (size_t)(bm + arow) * K + acol;
    const float* Bp = B + (size_t)brow * N + bn + bcol;

    for (int k0 = 0; k0 < K; k0 += 8) {
        float4 av = *(const float4*)(Ap + k0);
        float4 bv = *(const float4*)(Bp + (size_t)k0 * N);
        As[acol + 0][arow] = av.x;
        As[acol + 1][arow] = av.y;
        As[acol + 2][arow] = av.z;
        As[acol + 3][arow] = av.w;
        *(float4*)&Bs[brow][bcol] = bv;
        __syncthreads();

#pragma unroll
        for (int kk = 0; kk < 8; kk++) {
            float a[8], b[8];
#pragma unroll
            for (int i = 0; i < 8; i++) a[i] = As[kk][tm + i];
#pragma unroll
            for (int j = 0; j < 8; j++) b[j] = Bs[kk][tn + j];
#pragma unroll
            for (int i = 0; i < 8; i++)
#pragma unroll
                for (int j = 0; j < 8; j++)
                    acc[i][j] = fmaf(a[i], b[j], acc[i][j]);
        }
        __syncthreads();
    }

#pragma unroll
    for (int i = 0; i < 8; i++) {
        float* Cp = C + (size_t)(bm + tm + i) * N + bn + tn;
        float4 v0, v1;
        v0.x = acc[i][0]; v0.y = acc[i][1]; v0.z = acc[i][2]; v0.w = acc[i][3];
        v1.x = acc[i][4]; v1.y = acc[i][5]; v1.z = acc[i][6]; v1.w = acc[i][7];
        *(float4*)(Cp)     = v0;
        *(float4*)(Cp + 4) = v1;
    }
}

// ---------------------------------------------------------------------------
// Causal flash attention.
// Grid: (T/128 q-tiles, B*H). Block: 128 threads, 1 thread = 1 query row.
// q[64] and acc[64] in registers; K/V 64-row tiles in smem (broadcast reads);
// online softmax over score chunks of 16, scores staged in padded smem.
// qkv layout per row r=b*T+t: [0:1024)=Q heads, [1024:2048)=K, [2048:3072)=V.
// ---------------------------------------------------------------------------
__global__ __launch_bounds__(128)
void attn_kernel(const float* __restrict__ qkv, float* __restrict__ outp)
{
    __shared__ float Ks[64][64];
    __shared__ float Vs[64][64];
    __shared__ float Ss[128][17];   // pad 17 -> conflict-free per-thread rows

    const int qt = blockIdx.x;
    const int b  = blockIdx.y >> 4;
    const int h  = blockIdx.y & 15;
    const int t  = threadIdx.x;
    const int qrow = qt * 128 + t;

    const float* qbase = qkv + ((size_t)(b * T_ + qrow)) * QKV_N + h * DH_;
    float q[64];
#pragma unroll
    for (int d = 0; d < 64; d += 4) {
        float4 v = *(const float4*)(qbase + d);
        q[d] = v.x; q[d + 1] = v.y; q[d + 2] = v.z; q[d + 3] = v.w;
    }

    float acc[64];
#pragma unroll
    for (int d = 0; d < 64; d++) acc[d] = 0.f;
    float m = -1e30f, l = 0.f;

    const int ntiles = 2 * (qt + 1);   // causal: kv tiles up to (qt+1)*128
    for (int kt = 0; kt < ntiles; kt++) {
        const int s0 = kt * 64;
        __syncthreads();   // protect smem from previous iteration's readers
        // Load K and V tiles: 64 rows x 16 float4 each, 8 float4 per thread.
#pragma unroll
        for (int i = t; i < 64 * 16; i += 128) {
            const int r = i >> 4, c = (i & 15) << 2;
            const float* kv = qkv + ((size_t)(b * T_ + s0 + r)) * QKV_N + h * DH_ + c;
            *(float4*)&Ks[r][c] = *(const float4*)(kv + C_);
            *(float4*)&Vs[r][c] = *(const float4*)(kv + 2 * C_);
        }
        __syncthreads();
        if (s0 > qrow) continue;   // fully masked for this query row

#pragma unroll 1
        for (int c0 = 0; c0 < 64; c0 += 16) {
            float mloc = -1e30f;
#pragma unroll 4
            for (int j = 0; j < 16; j++) {
                const int kj = c0 + j;
                const float* kr = Ks[kj];
                float d0 = 0.f, d1 = 0.f, d2 = 0.f, d3 = 0.f;
#pragma unroll
                for (int d = 0; d < 64; d += 4) {
                    d0 = fmaf(q[d + 0], kr[d + 0], d0);
                    d1 = fmaf(q[d + 1], kr[d + 1], d1);
                    d2 = fmaf(q[d + 2], kr[d + 2], d2);
                    d3 = fmaf(q[d + 3], kr[d + 3], d3);
                }
                float dot = ((d0 + d1) + (d2 + d3)) * 0.125f;   // 1/sqrt(64)
                dot = (s0 + kj > qrow) ? -1e30f : dot;          // causal mask
                Ss[t][j] = dot;
                mloc = fmaxf(mloc, dot);
            }
            const float mnew  = fmaxf(m, mloc);
            const float alpha = __expf(m - mnew);
            m = mnew;
            l *= alpha;
#pragma unroll
            for (int d = 0; d < 64; d++) acc[d] *= alpha;
#pragma unroll 4
            for (int j = 0; j < 16; j++) {
                const float p = __expf(Ss[t][j] - m);
                l += p;
                const float* vr = Vs[c0 + j];
#pragma unroll
                for (int d = 0; d < 64; d++) acc[d] = fmaf(p, vr[d], acc[d]);
            }
        }
    }

    const float inv = 1.f / l;
    float* ob = outp + ((size_t)(b * T_ + qrow)) * C_ + h * DH_;
#pragma unroll
    for (int d = 0; d < 64; d += 4) {
        float4 v;
        v.x = acc[d] * inv; v.y = acc[d + 1] * inv;
        v.z = acc[d + 2] * inv; v.w = acc[d + 3] * inv;
        *(float4*)(ob + d) = v;
    }
}

// ---------------------------------------------------------------------------
// kernel_launch: QKV GEMM -> causal attention -> output GEMM
// Inputs: d_in[0]=x [4,2048,1024] f32, d_in[1]=W_qkv [1024,3072] f32,
//         d_in[2]=W_out [1024,1024] f32, d_in[3]=mask (deterministic tril,
//         implemented analytically -> unused).
// ---------------------------------------------------------------------------
extern "C" void kernel_launch(void* const* d_in, const int* in_sizes, int n_in,
                              void* d_out, int out_size)
{
    (void)in_sizes; (void)n_in; (void)out_size;
    const float* x    = (const float*)d_in[0];
    const float* Wqkv = (const float*)d_in[1];
    const float* Wout = (const float*)d_in[2];
    float* out = (float*)d_out;

    float* qkv = nullptr;
    float* att = nullptr;
    cudaGetSymbolAddress((void**)&qkv, g_qkv);
    cudaGetSymbolAddress((void**)&att, g_att);

    // 1) QKV projection: [8192,1024] @ [1024,3072]
    sgemm_kernel<<<dim3(QKV_N / 128, M_ROWS / 128), 256>>>(
        x, Wqkv, qkv, M_ROWS, QKV_N, C_);

    // 2) Causal multi-head attention
    attn_kernel<<<dim3(T_ / 128, B_ * H_), 128>>>(qkv, att);

    // 3) Output projection: [8192,1024] @ [1024,1024]
    sgemm_kernel<<<dim3(C_ / 128, M_ROWS / 128), 256>>>(
        att, Wout, out, M_ROWS, C_, C_);
}

// round 5
// speedup vs baseline: 1.5460x; 1.5460x over previous
#include <cuda_runtime.h>
#include <cuda_fp16.h>
#include <cstdint>

// Problem constants
#define B_  4
#define T_  2048
#define C_  1024
#define H_  16
#define DH_ 64
#define M_ROWS (B_ * T_)      // 8192
#define QKV_N  (3 * C_)       // 3072
#define K_DIM  1024           // K for both GEMMs

// ---------------------------------------------------------------------------
// Device scratch (sanctioned no-alloc path)
// ---------------------------------------------------------------------------
__device__ float g_qkv[(size_t)M_ROWS * QKV_N];        // 96 MB fp32
__device__ float g_att[(size_t)M_ROWS * C_];           // 32 MB fp32
__device__ __half g_ah[(size_t)M_ROWS * K_DIM];        // A hi (x / att)
__device__ __half g_al[(size_t)M_ROWS * K_DIM];        // A lo
__device__ __half g_wqh[(size_t)QKV_N * K_DIM];        // W_qkv^T hi [3072,1024]
__device__ __half g_wql[(size_t)QKV_N * K_DIM];
__device__ __half g_woh[(size_t)C_ * K_DIM];           // W_out^T hi [1024,1024]
__device__ __half g_wol[(size_t)C_ * K_DIM];

// ---------------------------------------------------------------------------
// Portable PTX helpers (sm_80-era: valid on target sm_103 without 'a')
// ---------------------------------------------------------------------------
__device__ __forceinline__ uint32_t smem_u32(const void* p) {
    uint32_t a;
    asm("{ .reg .u64 t; cvta.to.shared.u64 t, %1; cvt.u32.u64 %0, t; }" : "=r"(a) : "l"(p));
    return a;
}
#define CP_ASYNC16(dst, src) \
    asm volatile("cp.async.cg.shared.global [%0], [%1], 16;" :: "r"(dst), "l"(src))
#define CP_COMMIT() asm volatile("cp.async.commit_group;" ::: "memory")
#define CP_WAIT1()  asm volatile("cp.async.wait_group 1;" ::: "memory")
#define CP_WAIT0()  asm volatile("cp.async.wait_group 0;" ::: "memory")
#define LDSM4(r0, r1, r2, r3, addr) \
    asm volatile("ldmatrix.sync.aligned.m8n8.x4.shared.b16 {%0,%1,%2,%3}, [%4];" \
                 : "=r"(r0), "=r"(r1), "=r"(r2), "=r"(r3) : "r"(addr))

__device__ __forceinline__ void mma16816(float* c, const uint32_t* a, const uint32_t* b) {
    asm volatile(
        "mma.sync.aligned.m16n8k16.row.col.f32.f16.f16.f32 "
        "{%0,%1,%2,%3},{%4,%5,%6,%7},{%8,%9},{%0,%1,%2,%3};"
        : "+f"(c[0]), "+f"(c[1]), "+f"(c[2]), "+f"(c[3])
        : "r"(a[0]), "r"(a[1]), "r"(a[2]), "r"(a[3]), "r"(b[0]), "r"(b[1]));
}

// Swizzled 16B-chunk offset within a [128 rows x 4 chunks] (64B/row) tile.
// chunk' = chunk ^ ((row>>1)&3): any 8 consecutive rows at a fixed logical
// chunk hit 8 distinct 16B bank slots -> conflict-free ldmatrix.
__device__ __forceinline__ uint32_t sw_off(int r, int c) {
    return (uint32_t)((r << 2) | (c ^ ((r >> 1) & 3))) << 4;
}

// ---------------------------------------------------------------------------
// Split-conversion kernels (fp32 -> fp16 hi + fp16 lo)
// ---------------------------------------------------------------------------
__global__ __launch_bounds__(256)
void conv_split(const float4* __restrict__ src, __half2* __restrict__ hi,
                __half2* __restrict__ lo)
{
    const int i = blockIdx.x * 256 + threadIdx.x;
    float4 v = src[i];
    __half h0 = __float2half_rn(v.x), h1 = __float2half_rn(v.y);
    __half h2 = __float2half_rn(v.z), h3 = __float2half_rn(v.w);
    __half l0 = __float2half_rn(v.x - __half2float(h0));
    __half l1 = __float2half_rn(v.y - __half2float(h1));
    __half l2 = __float2half_rn(v.z - __half2float(h2));
    __half l3 = __float2half_rn(v.w - __half2float(h3));
    hi[2 * i]     = __halves2half2(h0, h1);
    hi[2 * i + 1] = __halves2half2(h2, h3);
    lo[2 * i]     = __halves2half2(l0, l1);
    lo[2 * i + 1] = __halves2half2(l2, l3);
}

// W[K,N] -> W^T hi/lo [N,K]
__global__ __launch_bounds__(256)
void transpose_split(const float* __restrict__ W, __half* __restrict__ Th,
                     __half* __restrict__ Tl, int K, int N)
{
    __shared__ float tile[32][33];
    const int n0 = blockIdx.x * 32, k0 = blockIdx.y * 32;
    const int tx = threadIdx.x & 31, ty = threadIdx.x >> 5;   // 32x8
#pragma unroll
    for (int j = 0; j < 32; j += 8)
        tile[ty + j][tx] = W[(size_t)(k0 + ty + j) * N + n0 + tx];
    __syncthreads();
#pragma unroll
    for (int j = 0; j < 32; j += 8) {
        float v = tile[tx][ty + j];
        __half h = __float2half_rn(v);
        __half l = __float2half_rn(v - __half2float(h));
        size_t o = (size_t)(n0 + ty + j) * K + k0 + tx;
        Th[o] = h; Tl[o] = l;
    }
}

// ---------------------------------------------------------------------------
// HMMA split-fp16 GEMM: C[M,N] = A[M,K] @ Bt[N,K]^T, fp32-grade accuracy.
// 128x128 CTA tile, BK=32, 256 threads (8 warps, 4x2), double-buffered
// cp.async stages, ldmatrix fragment loads, m16n8k16 f16->f32 mma.
// ---------------------------------------------------------------------------
#define STG_BYTES 32768               // 4 arrays x (128 x 64B)
#define HG_DYN    (2 * STG_BYTES)

__device__ __forceinline__ void load_stage(
    const __half* __restrict__ Ah, const __half* __restrict__ Al,
    const __half* __restrict__ Bh, const __half* __restrict__ Bl,
    int bm, int bn, int k0, uint32_t sbase, int tid)
{
#pragma unroll
    for (int i = 0; i < 2; i++) {
        const int idx = tid + i * 256;            // 0..511 chunk id
        const int r = idx >> 2;
        const int c = idx & 3;
        const uint32_t so = sw_off(r, c);
        const size_t goA = (size_t)(bm + r) * K_DIM + k0 + c * 8;
        const size_t goB = (size_t)(bn + r) * K_DIM + k0 + c * 8;
        CP_ASYNC16(sbase +         so, Ah + goA);
        CP_ASYNC16(sbase + 8192u + so, Al + goA);
        CP_ASYNC16(sbase + 16384u + so, Bh + goB);
        CP_ASYNC16(sbase + 24576u + so, Bl + goB);
    }
}

__global__ __launch_bounds__(256)
void hmma_gemm(const __half* __restrict__ Ah, const __half* __restrict__ Al,
               const __half* __restrict__ Bh, const __half* __restrict__ Bl,
               float* __restrict__ C, int N)
{
    extern __shared__ __align__(16) char sm_raw[];
    const int tid  = threadIdx.x;
    const int lane = tid & 31;
    const int wid  = tid >> 5;
    const int wr   = wid & 3;        // warp M band (32 rows)
    const int wc   = wid >> 2;       // warp N band (64 cols)
    const int bm = blockIdx.y * 128, bn = blockIdx.x * 128;

    const uint32_t s0 = smem_u32(sm_raw);

    float acc[2][8][4];
#pragma unroll
    for (int i = 0; i < 2; i++)
#pragma unroll
        for (int j = 0; j < 8; j++)
#pragma unroll
            for (int q = 0; q < 4; q++) acc[i][j][q] = 0.f;

    // ldmatrix lane-address components (constant across iterations)
    const int rA_base = wr * 32 + ((lane >> 3) & 1) * 8 + (lane & 7);
    const int cA_half = lane >> 4;                 // k-half select
    const int rB_base = wc * 64 + ((lane >> 4) ? 8 : 0) + (lane & 7);
    const int cB_half = (lane >> 3) & 1;

    // Prologue
    load_stage(Ah, Al, Bh, Bl, bm, bn, 0, s0, tid);
    CP_COMMIT();

    constexpr int NIT = K_DIM / 32;   // 32
    for (int it = 0; it < NIT; it++) {
        if (it + 1 < NIT) {
            load_stage(Ah, Al, Bh, Bl, bm, bn, (it + 1) * 32,
                       s0 + (uint32_t)(((it + 1) & 1) * STG_BYTES), tid);
            CP_COMMIT();
            CP_WAIT1();
        } else {
            CP_WAIT0();
        }
        __syncthreads();

        const uint32_t sa = s0 + (uint32_t)((it & 1) * STG_BYTES);
#pragma unroll
        for (int s = 0; s < 2; s++) {   // two k16 steps per BK=32
            uint32_t afh[2][4], afl[2][4], bfh[8][2], bfl[8][2];
            const int cA = s * 2 + cA_half;
            const int cB = s * 2 + cB_half;
#pragma unroll
            for (int mt = 0; mt < 2; mt++) {
                const uint32_t oa = sw_off(rA_base + mt * 16, cA);
                LDSM4(afh[mt][0], afh[mt][1], afh[mt][2], afh[mt][3], sa + oa);
                LDSM4(afl[mt][0], afl[mt][1], afl[mt][2], afl[mt][3], sa + 8192u + oa);
            }
#pragma unroll
            for (int np = 0; np < 4; np++) {
                const uint32_t ob = sw_off(rB_base + np * 16, cB);
                uint32_t t0, t1, t2, t3;
                LDSM4(t0, t1, t2, t3, sa + 16384u + ob);
                bfh[np * 2][0] = t0; bfh[np * 2][1] = t1;
                bfh[np * 2 + 1][0] = t2; bfh[np * 2 + 1][1] = t3;
                LDSM4(t0, t1, t2, t3, sa + 24576u + ob);
                bfl[np * 2][0] = t0; bfl[np * 2][1] = t1;
                bfl[np * 2 + 1][0] = t2; bfl[np * 2 + 1][1] = t3;
            }
#pragma unroll
            for (int mt = 0; mt < 2; mt++)
#pragma unroll
                for (int nt = 0; nt < 8; nt++) {
                    mma16816(acc[mt][nt], afh[mt], bfh[nt]);   // hi*hi
                    mma16816(acc[mt][nt], afh[mt], bfl[nt]);   // hi*lo
                    mma16816(acc[mt][nt], afl[mt], bfh[nt]);   // lo*hi
                }
        }
        __syncthreads();
    }

    // Epilogue: direct fp32 stores (float2 per fragment half)
#pragma unroll
    for (int mt = 0; mt < 2; mt++) {
        const int row = bm + wr * 32 + mt * 16 + (lane >> 2);
#pragma unroll
        for (int nt = 0; nt < 8; nt++) {
            const int col = bn + wc * 64 + nt * 8 + (lane & 3) * 2;
            float* p = C + (size_t)row * N + col;
            float2 v0; v0.x = acc[mt][nt][0]; v0.y = acc[mt][nt][1];
            float2 v1; v1.x = acc[mt][nt][2]; v1.y = acc[mt][nt][3];
            *(float2*)p = v0;
            *(float2*)(p + (size_t)8 * N) = v1;
        }
    }
}

// ---------------------------------------------------------------------------
// Causal flash attention (unchanged, known-good).
// ---------------------------------------------------------------------------
__global__ __launch_bounds__(128)
void attn_kernel(const float* __restrict__ qkv, float* __restrict__ outp)
{
    __shared__ float Ks[64][64];
    __shared__ float Vs[64][64];
    __shared__ float Ss[128][17];

    const int qt = blockIdx.x;
    const int b  = blockIdx.y >> 4;
    const int h  = blockIdx.y & 15;
    const int t  = threadIdx.x;
    const int qrow = qt * 128 + t;

    const float* qbase = qkv + ((size_t)(b * T_ + qrow)) * QKV_N + h * DH_;
    float q[64];
#pragma unroll
    for (int d = 0; d < 64; d += 4) {
        float4 v = *(const float4*)(qbase + d);
        q[d] = v.x; q[d + 1] = v.y; q[d + 2] = v.z; q[d + 3] = v.w;
    }

    float acc[64];
#pragma unroll
    for (int d = 0; d < 64; d++) acc[d] = 0.f;
    float m = -1e30f, l = 0.f;

    const int ntiles = 2 * (qt + 1);
    for (int kt = 0; kt < ntiles; kt++) {
        const int s0 = kt * 64;
        __syncthreads();
#pragma unroll
        for (int i = t; i < 64 * 16; i += 128) {
            const int r = i >> 4, c = (i & 15) << 2;
            const float* kv = qkv + ((size_t)(b * T_ + s0 + r)) * QKV_N + h * DH_ + c;
            *(float4*)&Ks[r][c] = *(const float4*)(kv + C_);
            *(float4*)&Vs[r][c] = *(const float4*)(kv + 2 * C_);
        }
        __syncthreads();
        if (s0 > qrow) continue;

#pragma unroll 1
        for (int c0 = 0; c0 < 64; c0 += 16) {
            float mloc = -1e30f;
#pragma unroll 4
            for (int j = 0; j < 16; j++) {
                const int kj = c0 + j;
                const float* kr = Ks[kj];
                float d0 = 0.f, d1 = 0.f, d2 = 0.f, d3 = 0.f;
#pragma unroll
                for (int d = 0; d < 64; d += 4) {
                    d0 = fmaf(q[d + 0], kr[d + 0], d0);
                    d1 = fmaf(q[d + 1], kr[d + 1], d1);
                    d2 = fmaf(q[d + 2], kr[d + 2], d2);
                    d3 = fmaf(q[d + 3], kr[d + 3], d3);
                }
                float dot = ((d0 + d1) + (d2 + d3)) * 0.125f;
                dot = (s0 + kj > qrow) ? -1e30f : dot;
                Ss[t][j] = dot;
                mloc = fmaxf(mloc, dot);
            }
            const float mnew  = fmaxf(m, mloc);
            const float alpha = __expf(m - mnew);
            m = mnew;
            l *= alpha;
#pragma unroll
            for (int d = 0; d < 64; d++) acc[d] *= alpha;
#pragma unroll 4
            for (int j = 0; j < 16; j++) {
                const float p = __expf(Ss[t][j] - m);
                l += p;
                const float* vr = Vs[c0 + j];
#pragma unroll
                for (int d = 0; d < 64; d++) acc[d] = fmaf(p, vr[d], acc[d]);
            }
        }
    }

    const float inv = 1.f / l;
    float* ob = outp + ((size_t)(b * T_ + qrow)) * C_ + h * DH_;
#pragma unroll
    for (int d = 0; d < 64; d += 4) {
        float4 v;
        v.x = acc[d] * inv; v.y = acc[d + 1] * inv;
        v.z = acc[d + 2] * inv; v.w = acc[d + 3] * inv;
        *(float4*)(ob + d) = v;
    }
}

// ---------------------------------------------------------------------------
// kernel_launch
// ---------------------------------------------------------------------------
extern "C" void kernel_launch(void* const* d_in, const int* in_sizes, int n_in,
                              void* d_out, int out_size)
{
    (void)in_sizes; (void)n_in; (void)out_size;
    const float* x    = (const float*)d_in[0];
    const float* Wqkv = (const float*)d_in[1];
    const float* Wout = (const float*)d_in[2];
    float* out = (float*)d_out;

    float *qkv, *att;
    __half *ah, *al, *wqh, *wql, *woh, *wol;
    cudaGetSymbolAddress((void**)&qkv, g_qkv);
    cudaGetSymbolAddress((void**)&att, g_att);
    cudaGetSymbolAddress((void**)&ah,  g_ah);
    cudaGetSymbolAddress((void**)&al,  g_al);
    cudaGetSymbolAddress((void**)&wqh, g_wqh);
    cudaGetSymbolAddress((void**)&wql, g_wql);
    cudaGetSymbolAddress((void**)&woh, g_woh);
    cudaGetSymbolAddress((void**)&wol, g_wol);

    cudaFuncSetAttribute(hmma_gemm, cudaFuncAttributeMaxDynamicSharedMemorySize, HG_DYN);

    const int n_elems4 = (M_ROWS * K_DIM) / 4;

    // 0) Split-convert x and transposed weights to fp16 hi/lo
    conv_split<<<n_elems4 / 256, 256>>>((const float4*)x, (__half2*)ah, (__half2*)al);
    transpose_split<<<dim3(QKV_N / 32, K_DIM / 32), 256>>>(Wqkv, wqh, wql, K_DIM, QKV_N);
    transpose_split<<<dim3(C_ / 32, K_DIM / 32), 256>>>(Wout, woh, wol, K_DIM, C_);

    // 1) QKV projection on tensor cores (HMMA): [8192,1024] @ [1024,3072]
    hmma_gemm<<<dim3(QKV_N / 128, M_ROWS / 128), 256, HG_DYN>>>(ah, al, wqh, wql, qkv, QKV_N);

    // 2) Causal multi-head attention (fp32 SIMT)
    attn_kernel<<<dim3(T_ / 128, B_ * H_), 128>>>(qkv, att);

    // 3) Split-convert attention output, then output projection
    conv_split<<<n_elems4 / 256, 256>>>((const float4*)att, (__half2*)ah, (__half2*)al);
    hmma_gemm<<<dim3(C_ / 128, M_ROWS / 128), 256, HG_DYN>>>(ah, al, woh, wol, out, C_);
}

// round 8
// speedup vs baseline: 3.4617x; 2.2391x over previous
#include <cuda_runtime.h>
#include <cuda_fp16.h>
#include <cstdint>

// Problem constants
#define B_  4
#define T_  2048
#define C_  1024
#define H_  16
#define DH_ 64
#define M_ROWS (B_ * T_)      // 8192
#define QKV_N  (3 * C_)       // 3072
#define K_DIM  1024

// ---------------------------------------------------------------------------
// Device scratch
// ---------------------------------------------------------------------------
__device__ float g_qkv[(size_t)M_ROWS * QKV_N];        // 96 MB fp32 (QKV GEMM out)
__device__ __half g_ah[(size_t)M_ROWS * K_DIM];        // A hi (x, later O)
__device__ __half g_al[(size_t)M_ROWS * K_DIM];        // A lo
__device__ __half g_wqh[(size_t)QKV_N * K_DIM];        // W_qkv^T hi
__device__ __half g_wql[(size_t)QKV_N * K_DIM];
__device__ __half g_woh[(size_t)C_ * K_DIM];           // W_out^T hi
__device__ __half g_wol[(size_t)C_ * K_DIM];
// per-head fp16 hi/lo: q,k as [bh][T][64]; v transposed [bh][64][T]
__device__ __half g_qh[(size_t)B_ * H_ * T_ * DH_];
__device__ __half g_ql[(size_t)B_ * H_ * T_ * DH_];
__device__ __half g_kh[(size_t)B_ * H_ * T_ * DH_];
__device__ __half g_kl[(size_t)B_ * H_ * T_ * DH_];
__device__ __half g_vth[(size_t)B_ * H_ * DH_ * T_];
__device__ __half g_vtl[(size_t)B_ * H_ * DH_ * T_];

// ---------------------------------------------------------------------------
// Portable PTX helpers (sm_80-era: valid on plain sm_103 target)
// ---------------------------------------------------------------------------
__device__ __forceinline__ uint32_t smem_u32(const void* p) {
    uint32_t a;
    asm("{ .reg .u64 t; cvta.to.shared.u64 t, %1; cvt.u32.u64 %0, t; }" : "=r"(a) : "l"(p));
    return a;
}
#define CP_ASYNC16(dst, src) \
    asm volatile("cp.async.cg.shared.global [%0], [%1], 16;" :: "r"(dst), "l"(src))
#define CP_COMMIT() asm volatile("cp.async.commit_group;" ::: "memory")
#define CP_WAIT1()  asm volatile("cp.async.wait_group 1;" ::: "memory")
#define CP_WAIT0()  asm volatile("cp.async.wait_group 0;" ::: "memory")
#define LDSM4(r0, r1, r2, r3, addr) \
    asm volatile("ldmatrix.sync.aligned.m8n8.x4.shared.b16 {%0,%1,%2,%3}, [%4];" \
                 : "=r"(r0), "=r"(r1), "=r"(r2), "=r"(r3) : "r"(addr))

__device__ __forceinline__ void mma16816(float* c, const uint32_t* a, const uint32_t* b) {
    asm volatile(
        "mma.sync.aligned.m16n8k16.row.col.f32.f16.f16.f32 "
        "{%0,%1,%2,%3},{%4,%5,%6,%7},{%8,%9},{%0,%1,%2,%3};"
        : "+f"(c[0]), "+f"(c[1]), "+f"(c[2]), "+f"(c[3])
        : "r"(a[0]), "r"(a[1]), "r"(a[2]), "r"(a[3]), "r"(b[0]), "r"(b[1]));
}

// Swizzle for 64B-row tiles (GEMM: [128 rows x 4 chunks])
__device__ __forceinline__ uint32_t sw_off(int r, int c) {
    return (uint32_t)((r << 2) | (c ^ ((r >> 1) & 3))) << 4;
}
// Swizzle for 128B-row tiles (attention: [64 rows x 8 chunks])
__device__ __forceinline__ uint32_t swk(int r, int c) {
    return (uint32_t)((r << 3) | (c ^ (r & 7))) << 4;
}
__device__ __forceinline__ uint32_t pack_h2(__half a, __half b) {
    __half2 h = __halves2half2(a, b);
    return *(uint32_t*)&h;
}

// ---------------------------------------------------------------------------
// Split-conversion kernels
// ---------------------------------------------------------------------------
__global__ __launch_bounds__(256)
void conv_split(const float4* __restrict__ src, __half2* __restrict__ hi,
                __half2* __restrict__ lo)
{
    const int i = blockIdx.x * 256 + threadIdx.x;
    float4 v = src[i];
    __half h0 = __float2half_rn(v.x), h1 = __float2half_rn(v.y);
    __half h2 = __float2half_rn(v.z), h3 = __float2half_rn(v.w);
    __half l0 = __float2half_rn(v.x - __half2float(h0));
    __half l1 = __float2half_rn(v.y - __half2float(h1));
    __half l2 = __float2half_rn(v.z - __half2float(h2));
    __half l3 = __float2half_rn(v.w - __half2float(h3));
    hi[2 * i]     = __halves2half2(h0, h1);
    hi[2 * i + 1] = __halves2half2(h2, h3);
    lo[2 * i]     = __halves2half2(l0, l1);
    lo[2 * i + 1] = __halves2half2(l2, l3);
}

__global__ __launch_bounds__(256)
void transpose_split(const float* __restrict__ W, __half* __restrict__ Th,
                     __half* __restrict__ Tl, int K, int N)
{
    __shared__ float tile[32][33];
    const int n0 = blockIdx.x * 32, k0 = blockIdx.y * 32;
    const int tx = threadIdx.x & 31, ty = threadIdx.x >> 5;
#pragma unroll
    for (int j = 0; j < 32; j += 8)
        tile[ty + j][tx] = W[(size_t)(k0 + ty + j) * N + n0 + tx];
    __syncthreads();
#pragma unroll
    for (int j = 0; j < 32; j += 8) {
        float v = tile[tx][ty + j];
        __half h = __float2half_rn(v);
        __half l = __float2half_rn(v - __half2float(h));
        size_t o = (size_t)(n0 + ty + j) * K + k0 + tx;
        Th[o] = h; Tl[o] = l;
    }
}

// ---------------------------------------------------------------------------
// HMMA split-fp16 GEMM (validated R5 kernel, unchanged)
// ---------------------------------------------------------------------------
#define STG_BYTES 32768
#define HG_DYN    (2 * STG_BYTES)

__device__ __forceinline__ void load_stage(
    const __half* __restrict__ Ah, const __half* __restrict__ Al,
    const __half* __restrict__ Bh, const __half* __restrict__ Bl,
    int bm, int bn, int k0, uint32_t sbase, int tid)
{
#pragma unroll
    for (int i = 0; i < 2; i++) {
        const int idx = tid + i * 256;
        const int r = idx >> 2;
        const int c = idx & 3;
        const uint32_t so = sw_off(r, c);
        const size_t goA = (size_t)(bm + r) * K_DIM + k0 + c * 8;
        const size_t goB = (size_t)(bn + r) * K_DIM + k0 + c * 8;
        CP_ASYNC16(sbase +          so, Ah + goA);
        CP_ASYNC16(sbase + 8192u  + so, Al + goA);
        CP_ASYNC16(sbase + 16384u + so, Bh + goB);
        CP_ASYNC16(sbase + 24576u + so, Bl + goB);
    }
}

__global__ __launch_bounds__(256)
void hmma_gemm(const __half* __restrict__ Ah, const __half* __restrict__ Al,
               const __half* __restrict__ Bh, const __half* __restrict__ Bl,
               float* __restrict__ C, int N)
{
    extern __shared__ __align__(16) char sm_raw[];
    const int tid  = threadIdx.x;
    const int lane = tid & 31;
    const int wid  = tid >> 5;
    const int wr   = wid & 3;
    const int wc   = wid >> 2;
    const int bm = blockIdx.y * 128, bn = blockIdx.x * 128;
    const uint32_t s0 = smem_u32(sm_raw);

    float acc[2][8][4];
#pragma unroll
    for (int i = 0; i < 2; i++)
#pragma unroll
        for (int j = 0; j < 8; j++)
#pragma unroll
            for (int q = 0; q < 4; q++) acc[i][j][q] = 0.f;

    const int rA_base = wr * 32 + ((lane >> 3) & 1) * 8 + (lane & 7);
    const int cA_half = lane >> 4;
    const int rB_base = wc * 64 + ((lane >> 4) ? 8 : 0) + (lane & 7);
    const int cB_half = (lane >> 3) & 1;

    load_stage(Ah, Al, Bh, Bl, bm, bn, 0, s0, tid);
    CP_COMMIT();

    constexpr int NIT = K_DIM / 32;
    for (int it = 0; it < NIT; it++) {
        if (it + 1 < NIT) {
            load_stage(Ah, Al, Bh, Bl, bm, bn, (it + 1) * 32,
                       s0 + (uint32_t)(((it + 1) & 1) * STG_BYTES), tid);
            CP_COMMIT();
            CP_WAIT1();
        } else {
            CP_WAIT0();
        }
        __syncthreads();

        const uint32_t sa = s0 + (uint32_t)((it & 1) * STG_BYTES);
#pragma unroll
        for (int s = 0; s < 2; s++) {
            uint32_t afh[2][4], afl[2][4], bfh[8][2], bfl[8][2];
            const int cA = s * 2 + cA_half;
            const int cB = s * 2 + cB_half;
#pragma unroll
            for (int mt = 0; mt < 2; mt++) {
                const uint32_t oa = sw_off(rA_base + mt * 16, cA);
                LDSM4(afh[mt][0], afh[mt][1], afh[mt][2], afh[mt][3], sa + oa);
                LDSM4(afl[mt][0], afl[mt][1], afl[mt][2], afl[mt][3], sa + 8192u + oa);
            }
#pragma unroll
            for (int np = 0; np < 4; np++) {
                const uint32_t ob = sw_off(rB_base + np * 16, cB);
                uint32_t t0, t1, t2, t3;
                LDSM4(t0, t1, t2, t3, sa + 16384u + ob);
                bfh[np * 2][0] = t0; bfh[np * 2][1] = t1;
                bfh[np * 2 + 1][0] = t2; bfh[np * 2 + 1][1] = t3;
                LDSM4(t0, t1, t2, t3, sa + 24576u + ob);
                bfl[np * 2][0] = t0; bfl[np * 2][1] = t1;
                bfl[np * 2 + 1][0] = t2; bfl[np * 2 + 1][1] = t3;
            }
#pragma unroll
            for (int mt = 0; mt < 2; mt++)
#pragma unroll
                for (int nt = 0; nt < 8; nt++) {
                    mma16816(acc[mt][nt], afh[mt], bfh[nt]);
                    mma16816(acc[mt][nt], afh[mt], bfl[nt]);
                    mma16816(acc[mt][nt], afl[mt], bfh[nt]);
                }
        }
        __syncthreads();
    }

#pragma unroll
    for (int mt = 0; mt < 2; mt++) {
        const int row = bm + wr * 32 + mt * 16 + (lane >> 2);
#pragma unroll
        for (int nt = 0; nt < 8; nt++) {
            const int col = bn + wc * 64 + nt * 8 + (lane & 3) * 2;
            float* p = C + (size_t)row * N + col;
            float2 v0; v0.x = acc[mt][nt][0]; v0.y = acc[mt][nt][1];
            float2 v1; v1.x = acc[mt][nt][2]; v1.y = acc[mt][nt][3];
            *(float2*)p = v0;
            *(float2*)(p + (size_t)8 * N) = v1;
        }
    }
}

// ---------------------------------------------------------------------------
// prep_qkv: fp32 qkv -> per-head fp16 hi/lo.  Q scaled by 1/8; V transposed.
// Grid: (T/32, B*H), 256 threads.
// ---------------------------------------------------------------------------
__device__ __forceinline__ void split8_store(const float* v, float scale,
                                             __half* dh, __half* dl)
{
    __half th[8], tl[8];
#pragma unroll
    for (int i = 0; i < 8; i++) {
        float x = v[i] * scale;
        __half h = __float2half_rn(x);
        th[i] = h;
        tl[i] = __float2half_rn(x - __half2float(h));
    }
    *(uint4*)dh = *(uint4*)th;
    *(uint4*)dl = *(uint4*)tl;
}

__global__ __launch_bounds__(256)
void prep_qkv(const float* __restrict__ qkv,
              __half* __restrict__ qh, __half* __restrict__ ql,
              __half* __restrict__ kh, __half* __restrict__ kl,
              __half* __restrict__ vth, __half* __restrict__ vtl)
{
    __shared__ __half svh[64][33];
    __shared__ __half svl[64][33];
    const int bh = blockIdx.y, b = bh >> 4, h = bh & 15;
    const int t0 = blockIdx.x * 32;
    const int tl_ = threadIdx.x >> 3;
    const int d0  = (threadIdx.x & 7) * 8;
    const float* src = qkv + (size_t)(b * T_ + t0 + tl_) * QKV_N + h * 64 + d0;
    const size_t qo = (size_t)(bh * T_ + t0 + tl_) * 64 + d0;

    float vbuf[8];
    // Q (scale 0.125 folded)
    *(float4*)(vbuf)     = *(const float4*)(src);
    *(float4*)(vbuf + 4) = *(const float4*)(src + 4);
    split8_store(vbuf, 0.125f, qh + qo, ql + qo);
    // K
    *(float4*)(vbuf)     = *(const float4*)(src + 1024);
    *(float4*)(vbuf + 4) = *(const float4*)(src + 1028);
    split8_store(vbuf, 1.0f, kh + qo, kl + qo);
    // V -> smem (for transpose)
    *(float4*)(vbuf)     = *(const float4*)(src + 2048);
    *(float4*)(vbuf + 4) = *(const float4*)(src + 2052);
#pragma unroll
    for (int j = 0; j < 8; j++) {
        __half h16 = __float2half_rn(vbuf[j]);
        svh[d0 + j][tl_] = h16;
        svl[d0 + j][tl_] = __float2half_rn(vbuf[j] - __half2float(h16));
    }
    __syncthreads();
#pragma unroll
    for (int j = 0; j < 4; j++) {
        const int idx = threadIdx.x + j * 256;
        const int d = idx >> 4, tp = idx & 15;
        __half2 hv = __halves2half2(svh[d][2 * tp], svh[d][2 * tp + 1]);
        __half2 lv = __halves2half2(svl[d][2 * tp], svl[d][2 * tp + 1]);
        const size_t o = ((size_t)(bh * 64 + d) * T_ + t0 + 2 * tp) >> 1;
        ((__half2*)vth)[o] = hv;
        ((__half2*)vtl)[o] = lv;
    }
}

// ---------------------------------------------------------------------------
// HMMA causal flash attention.
// Grid (16 qblocks, 64 bh), 256 threads = 8 warps x 16 q rows.
// KV tiles of 64, double-buffered cp.async. Split-fp16 S and P for accuracy.
// Writes O directly as fp16 hi/lo (out-proj A operands).
// ---------------------------------------------------------------------------
#define ATT_STG 32768                      // Kh 8K | Kl 8K | Vh 8K | Vl 8K
#define ATT_DYN (2 * ATT_STG + 1024)

__device__ __forceinline__ void attn_load_stage(
    const __half* __restrict__ kh, const __half* __restrict__ kl,
    const __half* __restrict__ vh, const __half* __restrict__ vl,
    size_t kbase, size_t vbase, int kv0, uint32_t sb, int tid)
{
#pragma unroll
    for (int j = 0; j < 2; j++) {
        const int idx = tid + j * 256;          // 0..511
        const int r = idx >> 3, c = idx & 7;
        const uint32_t so = swk(r, c);
        const size_t ko = kbase + (size_t)(kv0 + r) * 64 + c * 8;
        const size_t vo = vbase + (size_t)r * T_ + kv0 + c * 8;
        CP_ASYNC16(sb +          so, kh + ko);
        CP_ASYNC16(sb + 8192u  + so, kl + ko);
        CP_ASYNC16(sb + 16384u + so, vh + vo);
        CP_ASYNC16(sb + 24576u + so, vl + vo);
    }
}

__global__ __launch_bounds__(256)
void attn_mma(const __half* __restrict__ qh_g, const __half* __restrict__ ql_g,
              const __half* __restrict__ kh_g, const __half* __restrict__ kl_g,
              const __half* __restrict__ vh_g, const __half* __restrict__ vl_g,
              __half* __restrict__ oh_g, __half* __restrict__ ol_g)
{
    extern __shared__ __align__(16) char smraw[];
    const uint32_t s0r = smem_u32(smraw);
    const uint32_t s0  = (s0r + 1023u) & ~1023u;

    const int tid = threadIdx.x, lane = tid & 31, w = tid >> 5;
    const int qb = blockIdx.x, bh = blockIdx.y;
    const int b = bh >> 4, h = bh & 15;
    const int qw  = qb * 128 + w * 16;          // warp q-row base
    const int qr0 = qw + (lane >> 2);           // thread row (and +8)

    // --- Q fragments (A operand layout) straight from global ---
    uint32_t qfh[4][4], qfl[4][4];
    {
        const size_t base = (size_t)bh * T_ * 64;
        const __half* qp = qh_g + base;
        const __half* lp = ql_g + base;
        const int klo = (lane & 3) << 1;
        const size_t r0o = (size_t)qr0 * 64, r1o = (size_t)(qr0 + 8) * 64;
#pragma unroll
        for (int kd = 0; kd < 4; kd++) {
            const int kk = kd * 16 + klo;
            qfh[kd][0] = *(const uint32_t*)(qp + r0o + kk);
            qfh[kd][1] = *(const uint32_t*)(qp + r1o + kk);
            qfh[kd][2] = *(const uint32_t*)(qp + r0o + kk + 8);
            qfh[kd][3] = *(const uint32_t*)(qp + r1o + kk + 8);
            qfl[kd][0] = *(const uint32_t*)(lp + r0o + kk);
            qfl[kd][1] = *(const uint32_t*)(lp + r1o + kk);
            qfl[kd][2] = *(const uint32_t*)(lp + r0o + kk + 8);
            qfl[kd][3] = *(const uint32_t*)(lp + r1o + kk + 8);
        }
    }

    float accO[8][4];
#pragma unroll
    for (int i = 0; i < 8; i++)
#pragma unroll
        for (int j = 0; j < 4; j++) accO[i][j] = 0.f;
    float m0 = -1e30f, m1 = -1e30f, l0 = 0.f, l1 = 0.f;

    const size_t kbase = (size_t)bh * T_ * 64;
    const size_t vbase = (size_t)bh * 64 * T_;
    const int ntk = 2 * (qb + 1);

    const int bRow = ((lane >> 4) << 3) | (lane & 7);
    const int bSel = (lane >> 3) & 1;

    attn_load_stage(kh_g, kl_g, vh_g, vl_g, kbase, vbase, 0, s0, tid);
    CP_COMMIT();

    for (int t = 0; t < ntk; t++) {
        if (t + 1 < ntk) {
            attn_load_stage(kh_g, kl_g, vh_g, vl_g, kbase, vbase, (t + 1) * 64,
                            s0 + (uint32_t)(((t + 1) & 1) * ATT_STG), tid);
            CP_COMMIT();
            CP_WAIT1();
        } else {
            CP_WAIT0();
        }
        __syncthreads();

        const uint32_t sb = s0 + (uint32_t)((t & 1) * ATT_STG);
        const int kv0 = t * 64;

        if (kv0 <= qw + 15) {
            // ---- S = Q K^T (split x3) ----
            float s[8][4];
#pragma unroll
            for (int i = 0; i < 8; i++)
#pragma unroll
                for (int j = 0; j < 4; j++) s[i][j] = 0.f;

#pragma unroll
            for (int kd = 0; kd < 4; kd++) {
#pragma unroll
                for (int np = 0; np < 4; np++) {
                    const uint32_t off = swk(np * 16 + bRow, kd * 2 + bSel);
                    uint32_t b0, b1, b2, b3, c0, c1, c2, c3;
                    LDSM4(b0, b1, b2, b3, sb + off);
                    LDSM4(c0, c1, c2, c3, sb + 8192u + off);
                    uint32_t Bh0[2] = {b0, b1}, Bh1[2] = {b2, b3};
                    uint32_t Bl0[2] = {c0, c1}, Bl1[2] = {c2, c3};
                    mma16816(s[2 * np],     qfh[kd], Bh0);
                    mma16816(s[2 * np],     qfl[kd], Bh0);
                    mma16816(s[2 * np],     qfh[kd], Bl0);
                    mma16816(s[2 * np + 1], qfh[kd], Bh1);
                    mma16816(s[2 * np + 1], qfl[kd], Bh1);
                    mma16816(s[2 * np + 1], qfh[kd], Bl1);
                }
            }

            // ---- causal mask (diagonal tiles only) ----
            if (kv0 + 63 > qw) {
#pragma unroll
                for (int nt = 0; nt < 8; nt++) {
                    const int col = kv0 + nt * 8 + ((lane & 3) << 1);
                    if (col     > qr0)     s[nt][0] = -1e30f;
                    if (col + 1 > qr0)     s[nt][1] = -1e30f;
                    if (col     > qr0 + 8) s[nt][2] = -1e30f;
                    if (col + 1 > qr0 + 8) s[nt][3] = -1e30f;
                }
            }

            // ---- online softmax ----
            float mx0 = -1e30f, mx1 = -1e30f;
#pragma unroll
            for (int nt = 0; nt < 8; nt++) {
                mx0 = fmaxf(mx0, fmaxf(s[nt][0], s[nt][1]));
                mx1 = fmaxf(mx1, fmaxf(s[nt][2], s[nt][3]));
            }
            mx0 = fmaxf(mx0, __shfl_xor_sync(0xffffffffu, mx0, 1));
            mx0 = fmaxf(mx0, __shfl_xor_sync(0xffffffffu, mx0, 2));
            mx1 = fmaxf(mx1, __shfl_xor_sync(0xffffffffu, mx1, 1));
            mx1 = fmaxf(mx1, __shfl_xor_sync(0xffffffffu, mx1, 2));
            const float mn0 = fmaxf(m0, mx0), mn1 = fmaxf(m1, mx1);
            const float a0 = __expf(m0 - mn0), a1 = __expf(m1 - mn1);
            m0 = mn0; m1 = mn1;
            l0 *= a0;  l1 *= a1;
#pragma unroll
            for (int nt = 0; nt < 8; nt++) {
                accO[nt][0] *= a0; accO[nt][1] *= a0;
                accO[nt][2] *= a1; accO[nt][3] *= a1;
            }

            uint32_t ph[4][4], pl[4][4];
            float sum0 = 0.f, sum1 = 0.f;
#pragma unroll
            for (int nt = 0; nt < 8; nt++) {
                const float p0 = __expf(s[nt][0] - m0);
                const float p1 = __expf(s[nt][1] - m0);
                const float p2 = __expf(s[nt][2] - m1);
                const float p3 = __expf(s[nt][3] - m1);
                sum0 += p0 + p1; sum1 += p2 + p3;
                const __half h0 = __float2half_rn(p0), h1 = __float2half_rn(p1);
                const __half h2 = __float2half_rn(p2), h3 = __float2half_rn(p3);
                const int kt = nt >> 1, rg = (nt & 1) * 2;
                ph[kt][rg]     = pack_h2(h0, h1);
                ph[kt][rg + 1] = pack_h2(h2, h3);
                pl[kt][rg]     = pack_h2(__float2half_rn(p0 - __half2float(h0)),
                                         __float2half_rn(p1 - __half2float(h1)));
                pl[kt][rg + 1] = pack_h2(__float2half_rn(p2 - __half2float(h2)),
                                         __float2half_rn(p3 - __half2float(h3)));
            }
            sum0 += __shfl_xor_sync(0xffffffffu, sum0, 1);
            sum0 += __shfl_xor_sync(0xffffffffu, sum0, 2);
            sum1 += __shfl_xor_sync(0xffffffffu, sum1, 1);
            sum1 += __shfl_xor_sync(0xffffffffu, sum1, 2);
            l0 += sum0; l1 += sum1;

            // ---- O += P V (split x3) ----
#pragma unroll
            for (int kt = 0; kt < 4; kt++) {
#pragma unroll
                for (int np = 0; np < 4; np++) {
                    const uint32_t off = swk(np * 16 + bRow, kt * 2 + bSel);
                    uint32_t v0, v1, v2, v3, u0, u1, u2, u3;
                    LDSM4(v0, v1, v2, v3, sb + 16384u + off);
                    LDSM4(u0, u1, u2, u3, sb + 24576u + off);
                    uint32_t Vh0[2] = {v0, v1}, Vh1[2] = {v2, v3};
                    uint32_t Vl0[2] = {u0, u1}, Vl1[2] = {u2, u3};
                    mma16816(accO[2 * np],     ph[kt], Vh0);
                    mma16816(accO[2 * np],     pl[kt], Vh0);
                    mma16816(accO[2 * np],     ph[kt], Vl0);
                    mma16816(accO[2 * np + 1], ph[kt], Vh1);
                    mma16816(accO[2 * np + 1], pl[kt], Vh1);
                    mma16816(accO[2 * np + 1], ph[kt], Vl1);
                }
            }
        }
        __syncthreads();
    }

    // ---- epilogue: normalize, split to fp16 hi/lo, store ----
    const float inv0 = 1.f / l0, inv1 = 1.f / l1;
    const size_t row0 = (size_t)(b * T_ + qr0) * C_ + h * 64;
    const size_t row1 = (size_t)(b * T_ + qr0 + 8) * C_ + h * 64;
#pragma unroll
    for (int nt = 0; nt < 8; nt++) {
        const int col = nt * 8 + ((lane & 3) << 1);
        const float o0 = accO[nt][0] * inv0, o1 = accO[nt][1] * inv0;
        const float o2 = accO[nt][2] * inv1, o3 = accO[nt][3] * inv1;
        const __half h0 = __float2half_rn(o0), h1 = __float2half_rn(o1);
        const __half h2 = __float2half_rn(o2), h3 = __float2half_rn(o3);
        *(uint32_t*)(oh_g + row0 + col) = pack_h2(h0, h1);
        *(uint32_t*)(ol_g + row0 + col) = pack_h2(__float2half_rn(o0 - __half2float(h0)),
                                                  __float2half_rn(o1 - __half2float(h1)));
        *(uint32_t*)(oh_g + row1 + col) = pack_h2(h2, h3);
        *(uint32_t*)(ol_g + row1 + col) = pack_h2(__float2half_rn(o2 - __half2float(h2)),
                                                  __float2half_rn(o3 - __half2float(h3)));
    }
}

// ---------------------------------------------------------------------------
// kernel_launch
// ---------------------------------------------------------------------------
extern "C" void kernel_launch(void* const* d_in, const int* in_sizes, int n_in,
                              void* d_out, int out_size)
{
    (void)in_sizes; (void)n_in; (void)out_size;
    const float* x    = (const float*)d_in[0];
    const float* Wqkv = (const float*)d_in[1];
    const float* Wout = (const float*)d_in[2];
    float* out = (float*)d_out;

    float* qkv;
    __half *ah, *al, *wqh, *wql, *woh, *wol, *qh, *ql, *kh, *kl, *vth, *vtl;
    cudaGetSymbolAddress((void**)&qkv, g_qkv);
    cudaGetSymbolAddress((void**)&ah,  g_ah);
    cudaGetSymbolAddress((void**)&al,  g_al);
    cudaGetSymbolAddress((void**)&wqh, g_wqh);
    cudaGetSymbolAddress((void**)&wql, g_wql);
    cudaGetSymbolAddress((void**)&woh, g_woh);
    cudaGetSymbolAddress((void**)&wol, g_wol);
    cudaGetSymbolAddress((void**)&qh,  g_qh);
    cudaGetSymbolAddress((void**)&ql,  g_ql);
    cudaGetSymbolAddress((void**)&kh,  g_kh);
    cudaGetSymbolAddress((void**)&kl,  g_kl);
    cudaGetSymbolAddress((void**)&vth, g_vth);
    cudaGetSymbolAddress((void**)&vtl, g_vtl);

    cudaFuncSetAttribute(hmma_gemm, cudaFuncAttributeMaxDynamicSharedMemorySize, HG_DYN);
    cudaFuncSetAttribute(attn_mma,  cudaFuncAttributeMaxDynamicSharedMemorySize, ATT_DYN);

    const int n_elems4 = (M_ROWS * K_DIM) / 4;

    // 0) Split-convert x and transposed weights to fp16 hi/lo
    conv_split<<<n_elems4 / 256, 256>>>((const float4*)x, (__half2*)ah, (__half2*)al);
    transpose_split<<<dim3(QKV_N / 32, K_DIM / 32), 256>>>(Wqkv, wqh, wql, K_DIM, QKV_N);
    transpose_split<<<dim3(C_ / 32, K_DIM / 32), 256>>>(Wout, woh, wol, K_DIM, C_);

    // 1) QKV projection (HMMA split-fp16)
    hmma_gemm<<<dim3(QKV_N / 128, M_ROWS / 128), 256, HG_DYN>>>(ah, al, wqh, wql, qkv, QKV_N);

    // 2) Split per-head Q/K/V to fp16 hi/lo (V transposed), Q pre-scaled
    prep_qkv<<<dim3(T_ / 32, B_ * H_), 256>>>(qkv, qh, ql, kh, kl, vth, vtl);

    // 3) Causal attention on tensor cores; O written as fp16 hi/lo into ah/al
    attn_mma<<<dim3(T_ / 128, B_ * H_), 256, ATT_DYN>>>(qh, ql, kh, kl, vth, vtl, ah, al);

    // 4) Output projection (HMMA split-fp16)
    hmma_gemm<<<dim3(C_ / 128, M_ROWS / 128), 256, HG_DYN>>>(ah, al, woh, wol, out, C_);
}